// round 14
// baseline (speedup 1.0000x reference)
#include <cuda_runtime.h>
#include <cuda_bf16.h>
#include <cstdint>
#include <cstddef>

#define NNODES 20000
#define NEDGES 200000
#define DIMC   256
#define INNERC 256
#define EDIMC  512
#define FFC    1024
#define OUTC   128

// ---------------------------------------------------------------------------
// Scratch (static device allocations — allowed)
// ---------------------------------------------------------------------------
__device__ float g_xn  [NNODES * DIMC];
__device__ float g_q   [NNODES * INNERC];
__device__ float g_kv  [NNODES * 2 * INNERC];
__device__ float g_e   [(size_t)NEDGES * INNERC];
__device__ float g_sim [NEDGES * 4];
__device__ float g_agg [NNODES * INNERC];
__device__ float g_y   [NNODES * DIMC];
__device__ float g_x   [NNODES * DIMC];
__device__ float g_ff  [NNODES * FFC];
__device__ int   g_deg   [NNODES];
__device__ int   g_rowptr[NNODES + 1];
__device__ int   g_cursor[NNODES];
__device__ int   g_col   [NEDGES];

// ---------------------------------------------------------------------------
// Helpers
// ---------------------------------------------------------------------------
__device__ __forceinline__ float gelu_f(float t) {
    // jax.nn.gelu default: tanh approximation
    float t3 = t * t * t;
    return 0.5f * t * (1.0f + tanhf(0.7978845608028654f * (t + 0.044715f * t3)));
}

// ---------------------------------------------------------------------------
// Generic fp32 GEMM: C[M,N] = A[M,K] @ W[K,N] + bias ; optional GELU epilogue.
// Requirements: N % 128 == 0, K % 8 == 0 (true for all call sites). M guarded.
// 128x128 tile, BK=8, 256 threads, 8x8 per thread.
// ---------------------------------------------------------------------------
template<int GELU>
__global__ __launch_bounds__(256)
void gemm_kernel(const float* __restrict__ A, const float* __restrict__ W,
                 const float* __restrict__ bias, float* __restrict__ C,
                 int M, int K, int N)
{
    __shared__ float As[8][128];
    __shared__ float Bs[8][128];

    const int tid  = threadIdx.x;
    const int row0 = blockIdx.y * 128;
    const int col0 = blockIdx.x * 128;
    const int ty = tid >> 4;        // 0..15
    const int tx = tid & 15;        // 0..15

    const int aRow = tid >> 1;          // 0..127
    const int aCol = (tid & 1) * 4;     // 0 or 4
    const int bRow = tid >> 5;          // 0..7
    const int bCol = (tid & 31) * 4;    // 0..124

    float acc[8][8];
#pragma unroll
    for (int i = 0; i < 8; i++)
#pragma unroll
        for (int j = 0; j < 8; j++) acc[i][j] = 0.0f;

    const bool aValid = (row0 + aRow) < M;
    const float* Aptr = A + (size_t)(row0 + aRow) * K + aCol;
    const float* Wptr = W + (size_t)bRow * N + col0 + bCol;

    for (int k0 = 0; k0 < K; k0 += 8) {
        float4 av = aValid ? *reinterpret_cast<const float4*>(Aptr + k0)
                           : make_float4(0.f, 0.f, 0.f, 0.f);
        float4 bv = *reinterpret_cast<const float4*>(Wptr + (size_t)k0 * N);
        As[aCol + 0][aRow] = av.x;
        As[aCol + 1][aRow] = av.y;
        As[aCol + 2][aRow] = av.z;
        As[aCol + 3][aRow] = av.w;
        *reinterpret_cast<float4*>(&Bs[bRow][bCol]) = bv;
        __syncthreads();

#pragma unroll
        for (int k = 0; k < 8; k++) {
            float ra[8], rb[8];
            *reinterpret_cast<float4*>(&ra[0]) = *reinterpret_cast<const float4*>(&As[k][ty * 8]);
            *reinterpret_cast<float4*>(&ra[4]) = *reinterpret_cast<const float4*>(&As[k][ty * 8 + 4]);
            *reinterpret_cast<float4*>(&rb[0]) = *reinterpret_cast<const float4*>(&Bs[k][tx * 8]);
            *reinterpret_cast<float4*>(&rb[4]) = *reinterpret_cast<const float4*>(&Bs[k][tx * 8 + 4]);
#pragma unroll
            for (int i = 0; i < 8; i++)
#pragma unroll
                for (int j = 0; j < 8; j++)
                    acc[i][j] = fmaf(ra[i], rb[j], acc[i][j]);
        }
        __syncthreads();
    }

#pragma unroll
    for (int i = 0; i < 8; i++) {
        int gr = row0 + ty * 8 + i;
        if (gr >= M) continue;
#pragma unroll
        for (int j = 0; j < 8; j += 4) {
            int gc = col0 + tx * 8 + j;
            float4 o;
            o.x = acc[i][j + 0] + bias[gc + 0];
            o.y = acc[i][j + 1] + bias[gc + 1];
            o.z = acc[i][j + 2] + bias[gc + 2];
            o.w = acc[i][j + 3] + bias[gc + 3];
            if (GELU) {
                o.x = gelu_f(o.x); o.y = gelu_f(o.y);
                o.z = gelu_f(o.z); o.w = gelu_f(o.w);
            }
            *reinterpret_cast<float4*>(C + (size_t)gr * N + gc) = o;
        }
    }
}

// ---------------------------------------------------------------------------
// LayerNorm: one warp per row (256 cols).
// ---------------------------------------------------------------------------
__global__ void ln_kernel(const float* __restrict__ x, const float* __restrict__ g,
                          const float* __restrict__ b, float* __restrict__ out, int rows)
{
    int r    = (blockIdx.x * blockDim.x + threadIdx.x) >> 5;
    int lane = threadIdx.x & 31;
    if (r >= rows) return;
    const float* xr = x + (size_t)r * DIMC;
    float v[8];
    float s = 0.f, s2 = 0.f;
#pragma unroll
    for (int i = 0; i < 8; i++) {
        v[i] = xr[lane + 32 * i];
        s  += v[i];
        s2 += v[i] * v[i];
    }
#pragma unroll
    for (int o = 16; o > 0; o >>= 1) {
        s  += __shfl_xor_sync(0xffffffffu, s,  o);
        s2 += __shfl_xor_sync(0xffffffffu, s2, o);
    }
    float mean = s * (1.f / 256.f);
    float var  = s2 * (1.f / 256.f) - mean * mean;
    float rs   = rsqrtf(var + 1e-5f);
    float* orow = out + (size_t)r * DIMC;
#pragma unroll
    for (int i = 0; i < 8; i++) {
        int c = lane + 32 * i;
        orow[c] = (v[i] - mean) * rs * g[c] + b[c];
    }
}

// ---------------------------------------------------------------------------
// Edge similarity: one warp per edge. sim[e][h] = scale * <q[dst], k[src]+e>
// ---------------------------------------------------------------------------
__global__ void sim_kernel(const float* __restrict__ q, const float* __restrict__ kv,
                           const float* __restrict__ ebuf, const int* __restrict__ src,
                           const int* __restrict__ dst, float* __restrict__ sim)
{
    int eid  = (blockIdx.x * blockDim.x + threadIdx.x) >> 5;
    int lane = threadIdx.x & 31;
    if (eid >= NEDGES) return;
    int s = src[eid], t = dst[eid];
    const float* qr = q    + (size_t)t   * INNERC;
    const float* kr = kv   + (size_t)s   * (2 * INNERC);
    const float* er = ebuf + (size_t)eid * INNERC;
    const float scale = 0.125f;  // 64^-0.5
#pragma unroll
    for (int h = 0; h < 4; h++) {
        int j = h * 64 + lane;
        float p = qr[j]      * (kr[j]      + er[j])
                + qr[j + 32] * (kr[j + 32] + er[j + 32]);
#pragma unroll
        for (int o = 16; o > 0; o >>= 1) p += __shfl_xor_sync(0xffffffffu, p, o);
        if (lane == 0) sim[eid * 4 + h] = p * scale;
    }
}

// ---------------------------------------------------------------------------
// Per-node segment softmax + weighted aggregation over incoming edges (CSR).
// One 256-thread block per node; thread = output channel; h = c/64.
// ---------------------------------------------------------------------------
__global__ __launch_bounds__(256)
void node_attn_kernel(const float* __restrict__ kv, const float* __restrict__ ebuf,
                      const float* __restrict__ sim, const int* __restrict__ rowptr,
                      const int* __restrict__ col, const int* __restrict__ src,
                      float* __restrict__ agg)
{
    int n = blockIdx.x;
    int start = rowptr[n], end = rowptr[n + 1];
    int tid = threadIdx.x;

    __shared__ float sm[4], sinv[4];
    __shared__ float w[64 * 4];
    __shared__ int esh[64], ssh[64];

    int wid = tid >> 5, lane = tid & 31;
    if (wid < 4) {
        float mx = -1e30f;
        for (int p = start + lane; p < end; p += 32)
            mx = fmaxf(mx, sim[col[p] * 4 + wid]);
#pragma unroll
        for (int o = 16; o > 0; o >>= 1) mx = fmaxf(mx, __shfl_xor_sync(0xffffffffu, mx, o));
        float dn = 0.f;
        for (int p = start + lane; p < end; p += 32)
            dn += __expf(sim[col[p] * 4 + wid] - mx);
#pragma unroll
        for (int o = 16; o > 0; o >>= 1) dn += __shfl_xor_sync(0xffffffffu, dn, o);
        if (lane == 0) {
            sm[wid]   = mx;
            sinv[wid] = (dn > 0.f) ? 1.f / dn : 0.f;
        }
    }
    __syncthreads();

    int c = tid, h = tid >> 6;
    float acc = 0.f;
    for (int base = start; base < end; base += 64) {
        int cnt = min(64, end - base);
        if (tid < cnt * 4) {
            int i = tid >> 2, hh = tid & 3;
            int eid = col[base + i];
            w[tid] = __expf(sim[eid * 4 + hh] - sm[hh]) * sinv[hh];
            if (hh == 0) { esh[i] = eid; ssh[i] = src[eid]; }
        }
        __syncthreads();
        for (int i = 0; i < cnt; i++) {
            int eid = esh[i], s = ssh[i];
            acc = fmaf(w[i * 4 + h],
                       kv[(size_t)s * (2 * INNERC) + INNERC + c] + ebuf[(size_t)eid * INNERC + c],
                       acc);
        }
        __syncthreads();
    }
    agg[(size_t)n * INNERC + c] = acc;
}

// ---------------------------------------------------------------------------
// Gated residual: x = y*g + x*(1-g), g = sigmoid(<[y,x,y-x], gw>). Warp per row.
// ---------------------------------------------------------------------------
__global__ void gated_residual_kernel(const float* __restrict__ y, float* __restrict__ x,
                                      const float* __restrict__ gw, int rows)
{
    int r    = (blockIdx.x * blockDim.x + threadIdx.x) >> 5;
    int lane = threadIdx.x & 31;
    if (r >= rows) return;
    const float* yr = y + (size_t)r * DIMC;
    float* xr = x + (size_t)r * DIMC;
    float yv[8], rv[8];
    float s = 0.f;
#pragma unroll
    for (int i = 0; i < 8; i++) {
        int c = lane + 32 * i;
        yv[i] = yr[c];
        rv[i] = xr[c];
        s += yv[i] * (gw[c] + gw[512 + c]) + rv[i] * (gw[256 + c] - gw[512 + c]);
    }
#pragma unroll
    for (int o = 16; o > 0; o >>= 1) s += __shfl_xor_sync(0xffffffffu, s, o);
    float gate = 1.f / (1.f + __expf(-s));
#pragma unroll
    for (int i = 0; i < 8; i++) {
        int c = lane + 32 * i;
        xr[c] = yv[i] * gate + rv[i] * (1.f - gate);
    }
}

// ---------------------------------------------------------------------------
// CSR build
// ---------------------------------------------------------------------------
__global__ void zero_int_kernel(int* p, int n) {
    int i = blockIdx.x * blockDim.x + threadIdx.x;
    if (i < n) p[i] = 0;
}

__global__ void count_deg_kernel(const int* __restrict__ dst, int* __restrict__ deg) {
    int e = blockIdx.x * blockDim.x + threadIdx.x;
    if (e < NEDGES) atomicAdd(&deg[dst[e]], 1);
}

__global__ void scan_deg_kernel(const int* __restrict__ deg, int* __restrict__ rowptr,
                                int* __restrict__ cursor)
{
    __shared__ int temp[1024];
    __shared__ int carry;
    int tid = threadIdx.x;
    if (tid == 0) carry = 0;
    __syncthreads();
    for (int base = 0; base < NNODES; base += 1024) {
        int i = base + tid;
        int v = (i < NNODES) ? deg[i] : 0;
        temp[tid] = v;
        __syncthreads();
        for (int off = 1; off < 1024; off <<= 1) {
            int t = (tid >= off) ? temp[tid - off] : 0;
            __syncthreads();
            temp[tid] += t;
            __syncthreads();
        }
        int excl = temp[tid] - v;
        if (i < NNODES) {
            int r = carry + excl;
            rowptr[i] = r;
            cursor[i] = r;
        }
        __syncthreads();
        if (tid == 1023) carry += temp[1023];
        __syncthreads();
    }
    if (tid == 0) rowptr[NNODES] = carry;
}

__global__ void fill_col_kernel(const int* __restrict__ dst, int* __restrict__ cursor,
                                int* __restrict__ col)
{
    int e = blockIdx.x * blockDim.x + threadIdx.x;
    if (e < NEDGES) {
        int pos = atomicAdd(&cursor[dst[e]], 1);
        col[pos] = e;
    }
}

__global__ void copy_kernel(const float* __restrict__ in, float* __restrict__ out, int n) {
    for (int i = blockIdx.x * blockDim.x + threadIdx.x; i < n; i += gridDim.x * blockDim.x)
        out[i] = in[i];
}

// ---------------------------------------------------------------------------
// Host launch
// ---------------------------------------------------------------------------
extern "C" void kernel_launch(void* const* d_in, const int* in_sizes, int n_in,
                              void* d_out, int out_size)
{
    const float* x         = (const float*)d_in[0];
    const float* edge_attr = (const float*)d_in[1];
    const int*   edge_idx  = (const int*)  d_in[2];
    const float* ln1_g = (const float*)d_in[3];
    const float* ln1_b = (const float*)d_in[4];
    const float* Wq  = (const float*)d_in[5];
    const float* bq  = (const float*)d_in[6];
    const float* Wkv = (const float*)d_in[7];
    const float* bkv = (const float*)d_in[8];
    const float* We  = (const float*)d_in[9];
    const float* be  = (const float*)d_in[10];
    const float* Wo  = (const float*)d_in[11];
    const float* bo  = (const float*)d_in[12];
    const float* gaw = (const float*)d_in[13];
    const float* ln2_g = (const float*)d_in[14];
    const float* ln2_b = (const float*)d_in[15];
    const float* Wff1 = (const float*)d_in[16];
    const float* bff1 = (const float*)d_in[17];
    const float* Wff2 = (const float*)d_in[18];
    const float* bff2 = (const float*)d_in[19];
    const float* gfw  = (const float*)d_in[20];
    const float* Wproj = (const float*)d_in[21];
    const float* bproj = (const float*)d_in[22];
    float* out = (float*)d_out;

    const int* src = edge_idx;
    const int* dst = edge_idx + NEDGES;

    float *xn, *qb, *kvb, *eb, *simb, *aggb, *yb, *xb, *ffb;
    int *deg, *rowptr, *cursor, *colb;
    cudaGetSymbolAddress((void**)&xn,     g_xn);
    cudaGetSymbolAddress((void**)&qb,     g_q);
    cudaGetSymbolAddress((void**)&kvb,    g_kv);
    cudaGetSymbolAddress((void**)&eb,     g_e);
    cudaGetSymbolAddress((void**)&simb,   g_sim);
    cudaGetSymbolAddress((void**)&aggb,   g_agg);
    cudaGetSymbolAddress((void**)&yb,     g_y);
    cudaGetSymbolAddress((void**)&xb,     g_x);
    cudaGetSymbolAddress((void**)&ffb,    g_ff);
    cudaGetSymbolAddress((void**)&deg,    g_deg);
    cudaGetSymbolAddress((void**)&rowptr, g_rowptr);
    cudaGetSymbolAddress((void**)&cursor, g_cursor);
    cudaGetSymbolAddress((void**)&colb,   g_col);

    const int TB = 256;
    const int edgeBlocks = (NEDGES + TB - 1) / TB;
    const int nodeBlocks = (NNODES + TB - 1) / TB;
    const int warpRowBlocks = (NNODES * 32 + TB - 1) / TB;   // warp-per-row kernels
    const int warpEdgeBlocks = ((size_t)NEDGES * 32 + TB - 1) / TB;

    // --- CSR build (cheap; rebuilt every call for determinism of work) ---
    zero_int_kernel<<<nodeBlocks, TB>>>(deg, NNODES);
    count_deg_kernel<<<edgeBlocks, TB>>>(dst, deg);
    scan_deg_kernel<<<1, 1024>>>(deg, rowptr, cursor);
    fill_col_kernel<<<edgeBlocks, TB>>>(dst, cursor, colb);

    // x working copy
    copy_kernel<<<512, TB>>>(x, xb, NNODES * DIMC);

    auto gemm_grid = [](int M, int N) { return dim3((unsigned)(N / 128), (unsigned)((M + 127) / 128)); };

    for (int d = 0; d < 2; d++) {
        // --- attention block ---
        ln_kernel<<<warpRowBlocks, TB>>>(xb, ln1_g + d * DIMC, ln1_b + d * DIMC, xn, NNODES);

        gemm_kernel<0><<<gemm_grid(NNODES, INNERC), TB>>>(
            xn, Wq + (size_t)d * DIMC * INNERC, bq + d * INNERC, qb, NNODES, DIMC, INNERC);
        gemm_kernel<0><<<gemm_grid(NNODES, 2 * INNERC), TB>>>(
            xn, Wkv + (size_t)d * DIMC * 2 * INNERC, bkv + d * 2 * INNERC, kvb, NNODES, DIMC, 2 * INNERC);
        gemm_kernel<0><<<gemm_grid(NEDGES, INNERC), TB>>>(
            edge_attr, We + (size_t)d * EDIMC * INNERC, be + d * INNERC, eb, NEDGES, EDIMC, INNERC);

        sim_kernel<<<warpEdgeBlocks, TB>>>(qb, kvb, eb, src, dst, simb);
        node_attn_kernel<<<NNODES, TB>>>(kvb, eb, simb, rowptr, colb, src, aggb);

        gemm_kernel<0><<<gemm_grid(NNODES, DIMC), TB>>>(
            aggb, Wo + (size_t)d * INNERC * DIMC, bo + d * DIMC, yb, NNODES, INNERC, DIMC);
        gated_residual_kernel<<<warpRowBlocks, TB>>>(yb, xb, gaw + d * 3 * DIMC, NNODES);

        // --- feedforward block ---
        ln_kernel<<<warpRowBlocks, TB>>>(xb, ln2_g + d * DIMC, ln2_b + d * DIMC, xn, NNODES);
        gemm_kernel<1><<<gemm_grid(NNODES, FFC), TB>>>(
            xn, Wff1 + (size_t)d * DIMC * FFC, bff1 + d * FFC, ffb, NNODES, DIMC, FFC);
        gemm_kernel<0><<<gemm_grid(NNODES, DIMC), TB>>>(
            ffb, Wff2 + (size_t)d * FFC * DIMC, bff2 + d * DIMC, yb, NNODES, FFC, DIMC);
        gated_residual_kernel<<<warpRowBlocks, TB>>>(yb, xb, gfw + d * 3 * DIMC, NNODES);
    }

    // --- output projection ---
    gemm_kernel<0><<<gemm_grid(NNODES, OUTC), TB>>>(
        xb, Wproj, bproj, out, NNODES, DIMC, OUTC);
}

// round 15
// speedup vs baseline: 1.0034x; 1.0034x over previous
#include <cuda_runtime.h>
#include <cuda_bf16.h>
#include <cstdint>
#include <cstddef>

#define NNODES 20000
#define NEDGES 200000
#define DIMC   256
#define INNERC 256
#define EDIMC  512
#define FFC    1024
#define OUTC   128

// ---------------------------------------------------------------------------
// Scratch (static device allocations — allowed)
// ---------------------------------------------------------------------------
__device__ float g_xn  [NNODES * DIMC];
__device__ float g_q   [NNODES * INNERC];
__device__ float g_kv  [NNODES * 2 * INNERC];
__device__ float g_e   [(size_t)NEDGES * INNERC];
__device__ float g_sim [NEDGES * 4];
__device__ float g_agg [NNODES * INNERC];
__device__ float g_y   [NNODES * DIMC];
__device__ float g_x   [NNODES * DIMC];
__device__ float g_ff  [NNODES * FFC];
__device__ int   g_deg   [NNODES];
__device__ int   g_rowptr[NNODES + 1];
__device__ int   g_cursor[NNODES];
__device__ int   g_col   [NEDGES];

// ---------------------------------------------------------------------------
// Helpers
// ---------------------------------------------------------------------------
__device__ __forceinline__ float gelu_f(float t) {
    // jax.nn.gelu default: tanh approximation
    float t3 = t * t * t;
    return 0.5f * t * (1.0f + tanhf(0.7978845608028654f * (t + 0.044715f * t3)));
}

// ---------------------------------------------------------------------------
// Generic fp32 GEMM: C[M,N] = A[M,K] @ W[K,N] + bias ; optional GELU epilogue.
// Requirements: N % 128 == 0, K % 8 == 0 (true for all call sites). M guarded.
// 128x128 tile, BK=8, 256 threads, 8x8 per thread.
// ---------------------------------------------------------------------------
template<int GELU>
__global__ __launch_bounds__(256)
void gemm_kernel(const float* __restrict__ A, const float* __restrict__ W,
                 const float* __restrict__ bias, float* __restrict__ C,
                 int M, int K, int N)
{
    __shared__ float As[8][128];
    __shared__ float Bs[8][128];

    const int tid  = threadIdx.x;
    const int row0 = blockIdx.y * 128;
    const int col0 = blockIdx.x * 128;
    const int ty = tid >> 4;        // 0..15
    const int tx = tid & 15;        // 0..15

    const int aRow = tid >> 1;          // 0..127
    const int aCol = (tid & 1) * 4;     // 0 or 4
    const int bRow = tid >> 5;          // 0..7
    const int bCol = (tid & 31) * 4;    // 0..124

    float acc[8][8];
#pragma unroll
    for (int i = 0; i < 8; i++)
#pragma unroll
        for (int j = 0; j < 8; j++) acc[i][j] = 0.0f;

    const bool aValid = (row0 + aRow) < M;
    const float* Aptr = A + (size_t)(row0 + aRow) * K + aCol;
    const float* Wptr = W + (size_t)bRow * N + col0 + bCol;

    for (int k0 = 0; k0 < K; k0 += 8) {
        float4 av = aValid ? *reinterpret_cast<const float4*>(Aptr + k0)
                           : make_float4(0.f, 0.f, 0.f, 0.f);
        float4 bv = *reinterpret_cast<const float4*>(Wptr + (size_t)k0 * N);
        As[aCol + 0][aRow] = av.x;
        As[aCol + 1][aRow] = av.y;
        As[aCol + 2][aRow] = av.z;
        As[aCol + 3][aRow] = av.w;
        *reinterpret_cast<float4*>(&Bs[bRow][bCol]) = bv;
        __syncthreads();

#pragma unroll
        for (int k = 0; k < 8; k++) {
            float ra[8], rb[8];
            *reinterpret_cast<float4*>(&ra[0]) = *reinterpret_cast<const float4*>(&As[k][ty * 8]);
            *reinterpret_cast<float4*>(&ra[4]) = *reinterpret_cast<const float4*>(&As[k][ty * 8 + 4]);
            *reinterpret_cast<float4*>(&rb[0]) = *reinterpret_cast<const float4*>(&Bs[k][tx * 8]);
            *reinterpret_cast<float4*>(&rb[4]) = *reinterpret_cast<const float4*>(&Bs[k][tx * 8 + 4]);
#pragma unroll
            for (int i = 0; i < 8; i++)
#pragma unroll
                for (int j = 0; j < 8; j++)
                    acc[i][j] = fmaf(ra[i], rb[j], acc[i][j]);
        }
        __syncthreads();
    }

#pragma unroll
    for (int i = 0; i < 8; i++) {
        int gr = row0 + ty * 8 + i;
        if (gr >= M) continue;
#pragma unroll
        for (int j = 0; j < 8; j += 4) {
            int gc = col0 + tx * 8 + j;
            float4 o;
            o.x = acc[i][j + 0] + bias[gc + 0];
            o.y = acc[i][j + 1] + bias[gc + 1];
            o.z = acc[i][j + 2] + bias[gc + 2];
            o.w = acc[i][j + 3] + bias[gc + 3];
            if (GELU) {
                o.x = gelu_f(o.x); o.y = gelu_f(o.y);
                o.z = gelu_f(o.z); o.w = gelu_f(o.w);
            }
            *reinterpret_cast<float4*>(C + (size_t)gr * N + gc) = o;
        }
    }
}

// ---------------------------------------------------------------------------
// LayerNorm: one warp per row (256 cols).
// ---------------------------------------------------------------------------
__global__ void ln_kernel(const float* __restrict__ x, const float* __restrict__ g,
                          const float* __restrict__ b, float* __restrict__ out, int rows)
{
    int r    = (blockIdx.x * blockDim.x + threadIdx.x) >> 5;
    int lane = threadIdx.x & 31;
    if (r >= rows) return;
    const float* xr = x + (size_t)r * DIMC;
    float v[8];
    float s = 0.f, s2 = 0.f;
#pragma unroll
    for (int i = 0; i < 8; i++) {
        v[i] = xr[lane + 32 * i];
        s  += v[i];
        s2 += v[i] * v[i];
    }
#pragma unroll
    for (int o = 16; o > 0; o >>= 1) {
        s  += __shfl_xor_sync(0xffffffffu, s,  o);
        s2 += __shfl_xor_sync(0xffffffffu, s2, o);
    }
    float mean = s * (1.f / 256.f);
    float var  = s2 * (1.f / 256.f) - mean * mean;
    float rs   = rsqrtf(var + 1e-5f);
    float* orow = out + (size_t)r * DIMC;
#pragma unroll
    for (int i = 0; i < 8; i++) {
        int c = lane + 32 * i;
        orow[c] = (v[i] - mean) * rs * g[c] + b[c];
    }
}

// ---------------------------------------------------------------------------
// Edge similarity: one warp per edge. sim[e][h] = scale * <q[dst], k[src]+e>
// ---------------------------------------------------------------------------
__global__ void sim_kernel(const float* __restrict__ q, const float* __restrict__ kv,
                           const float* __restrict__ ebuf, const int* __restrict__ src,
                           const int* __restrict__ dst, float* __restrict__ sim)
{
    int eid  = (blockIdx.x * blockDim.x + threadIdx.x) >> 5;
    int lane = threadIdx.x & 31;
    if (eid >= NEDGES) return;
    int s = src[eid], t = dst[eid];
    const float* qr = q    + (size_t)t   * INNERC;
    const float* kr = kv   + (size_t)s   * (2 * INNERC);
    const float* er = ebuf + (size_t)eid * INNERC;
    const float scale = 0.125f;  // 64^-0.5
#pragma unroll
    for (int h = 0; h < 4; h++) {
        int j = h * 64 + lane;
        float p = qr[j]      * (kr[j]      + er[j])
                + qr[j + 32] * (kr[j + 32] + er[j + 32]);
#pragma unroll
        for (int o = 16; o > 0; o >>= 1) p += __shfl_xor_sync(0xffffffffu, p, o);
        if (lane == 0) sim[eid * 4 + h] = p * scale;
    }
}

// ---------------------------------------------------------------------------
// Per-node segment softmax + weighted aggregation over incoming edges (CSR).
// One 256-thread block per node; thread = output channel; h = c/64.
// ---------------------------------------------------------------------------
__global__ __launch_bounds__(256)
void node_attn_kernel(const float* __restrict__ kv, const float* __restrict__ ebuf,
                      const float* __restrict__ sim, const int* __restrict__ rowptr,
                      const int* __restrict__ col, const int* __restrict__ src,
                      float* __restrict__ agg)
{
    int n = blockIdx.x;
    int start = rowptr[n], end = rowptr[n + 1];
    int tid = threadIdx.x;

    __shared__ float sm[4], sinv[4];
    __shared__ float w[64 * 4];
    __shared__ int esh[64], ssh[64];

    int wid = tid >> 5, lane = tid & 31;
    if (wid < 4) {
        float mx = -1e30f;
        for (int p = start + lane; p < end; p += 32)
            mx = fmaxf(mx, sim[col[p] * 4 + wid]);
#pragma unroll
        for (int o = 16; o > 0; o >>= 1) mx = fmaxf(mx, __shfl_xor_sync(0xffffffffu, mx, o));
        float dn = 0.f;
        for (int p = start + lane; p < end; p += 32)
            dn += __expf(sim[col[p] * 4 + wid] - mx);
#pragma unroll
        for (int o = 16; o > 0; o >>= 1) dn += __shfl_xor_sync(0xffffffffu, dn, o);
        if (lane == 0) {
            sm[wid]   = mx;
            sinv[wid] = (dn > 0.f) ? 1.f / dn : 0.f;
        }
    }
    __syncthreads();

    int c = tid, h = tid >> 6;
    float acc = 0.f;
    for (int base = start; base < end; base += 64) {
        int cnt = min(64, end - base);
        if (tid < cnt * 4) {
            int i = tid >> 2, hh = tid & 3;
            int eid = col[base + i];
            w[tid] = __expf(sim[eid * 4 + hh] - sm[hh]) * sinv[hh];
            if (hh == 0) { esh[i] = eid; ssh[i] = src[eid]; }
        }
        __syncthreads();
        for (int i = 0; i < cnt; i++) {
            int eid = esh[i], s = ssh[i];
            acc = fmaf(w[i * 4 + h],
                       kv[(size_t)s * (2 * INNERC) + INNERC + c] + ebuf[(size_t)eid * INNERC + c],
                       acc);
        }
        __syncthreads();
    }
    agg[(size_t)n * INNERC + c] = acc;
}

// ---------------------------------------------------------------------------
// Gated residual: x = y*g + x*(1-g), g = sigmoid(<[y,x,y-x], gw>). Warp per row.
// ---------------------------------------------------------------------------
__global__ void gated_residual_kernel(const float* __restrict__ y, float* __restrict__ x,
                                      const float* __restrict__ gw, int rows)
{
    int r    = (blockIdx.x * blockDim.x + threadIdx.x) >> 5;
    int lane = threadIdx.x & 31;
    if (r >= rows) return;
    const float* yr = y + (size_t)r * DIMC;
    float* xr = x + (size_t)r * DIMC;
    float yv[8], rv[8];
    float s = 0.f;
#pragma unroll
    for (int i = 0; i < 8; i++) {
        int c = lane + 32 * i;
        yv[i] = yr[c];
        rv[i] = xr[c];
        s += yv[i] * (gw[c] + gw[512 + c]) + rv[i] * (gw[256 + c] - gw[512 + c]);
    }
#pragma unroll
    for (int o = 16; o > 0; o >>= 1) s += __shfl_xor_sync(0xffffffffu, s, o);
    float gate = 1.f / (1.f + __expf(-s));
#pragma unroll
    for (int i = 0; i < 8; i++) {
        int c = lane + 32 * i;
        xr[c] = yv[i] * gate + rv[i] * (1.f - gate);
    }
}

// ---------------------------------------------------------------------------
// CSR build
// ---------------------------------------------------------------------------
__global__ void zero_int_kernel(int* p, int n) {
    int i = blockIdx.x * blockDim.x + threadIdx.x;
    if (i < n) p[i] = 0;
}

__global__ void count_deg_kernel(const int* __restrict__ dst, int* __restrict__ deg) {
    int e = blockIdx.x * blockDim.x + threadIdx.x;
    if (e < NEDGES) atomicAdd(&deg[dst[e]], 1);
}

__global__ void scan_deg_kernel(const int* __restrict__ deg, int* __restrict__ rowptr,
                                int* __restrict__ cursor)
{
    __shared__ int temp[1024];
    __shared__ int carry;
    int tid = threadIdx.x;
    if (tid == 0) carry = 0;
    __syncthreads();
    for (int base = 0; base < NNODES; base += 1024) {
        int i = base + tid;
        int v = (i < NNODES) ? deg[i] : 0;
        temp[tid] = v;
        __syncthreads();
        for (int off = 1; off < 1024; off <<= 1) {
            int t = (tid >= off) ? temp[tid - off] : 0;
            __syncthreads();
            temp[tid] += t;
            __syncthreads();
        }
        int excl = temp[tid] - v;
        if (i < NNODES) {
            int r = carry + excl;
            rowptr[i] = r;
            cursor[i] = r;
        }
        __syncthreads();
        if (tid == 1023) carry += temp[1023];
        __syncthreads();
    }
    if (tid == 0) rowptr[NNODES] = carry;
}

__global__ void fill_col_kernel(const int* __restrict__ dst, int* __restrict__ cursor,
                                int* __restrict__ col)
{
    int e = blockIdx.x * blockDim.x + threadIdx.x;
    if (e < NEDGES) {
        int pos = atomicAdd(&cursor[dst[e]], 1);
        col[pos] = e;
    }
}

__global__ void copy_kernel(const float* __restrict__ in, float* __restrict__ out, int n) {
    for (int i = blockIdx.x * blockDim.x + threadIdx.x; i < n; i += gridDim.x * blockDim.x)
        out[i] = in[i];
}

// ---------------------------------------------------------------------------
// Host launch
// ---------------------------------------------------------------------------
extern "C" void kernel_launch(void* const* d_in, const int* in_sizes, int n_in,
                              void* d_out, int out_size)
{
    const float* x         = (const float*)d_in[0];
    const float* edge_attr = (const float*)d_in[1];
    const int*   edge_idx  = (const int*)  d_in[2];
    const float* ln1_g = (const float*)d_in[3];
    const float* ln1_b = (const float*)d_in[4];
    const float* Wq  = (const float*)d_in[5];
    const float* bq  = (const float*)d_in[6];
    const float* Wkv = (const float*)d_in[7];
    const float* bkv = (const float*)d_in[8];
    const float* We  = (const float*)d_in[9];
    const float* be  = (const float*)d_in[10];
    const float* Wo  = (const float*)d_in[11];
    const float* bo  = (const float*)d_in[12];
    const float* gaw = (const float*)d_in[13];
    const float* ln2_g = (const float*)d_in[14];
    const float* ln2_b = (const float*)d_in[15];
    const float* Wff1 = (const float*)d_in[16];
    const float* bff1 = (const float*)d_in[17];
    const float* Wff2 = (const float*)d_in[18];
    const float* bff2 = (const float*)d_in[19];
    const float* gfw  = (const float*)d_in[20];
    const float* Wproj = (const float*)d_in[21];
    const float* bproj = (const float*)d_in[22];
    float* out = (float*)d_out;

    const int* src = edge_idx;
    const int* dst = edge_idx + NEDGES;

    float *xn, *qb, *kvb, *eb, *simb, *aggb, *yb, *xb, *ffb;
    int *deg, *rowptr, *cursor, *colb;
    cudaGetSymbolAddress((void**)&xn,     g_xn);
    cudaGetSymbolAddress((void**)&qb,     g_q);
    cudaGetSymbolAddress((void**)&kvb,    g_kv);
    cudaGetSymbolAddress((void**)&eb,     g_e);
    cudaGetSymbolAddress((void**)&simb,   g_sim);
    cudaGetSymbolAddress((void**)&aggb,   g_agg);
    cudaGetSymbolAddress((void**)&yb,     g_y);
    cudaGetSymbolAddress((void**)&xb,     g_x);
    cudaGetSymbolAddress((void**)&ffb,    g_ff);
    cudaGetSymbolAddress((void**)&deg,    g_deg);
    cudaGetSymbolAddress((void**)&rowptr, g_rowptr);
    cudaGetSymbolAddress((void**)&cursor, g_cursor);
    cudaGetSymbolAddress((void**)&colb,   g_col);

    const int TB = 256;
    const int edgeBlocks = (NEDGES + TB - 1) / TB;
    const int nodeBlocks = (NNODES + TB - 1) / TB;
    const int warpRowBlocks = (NNODES * 32 + TB - 1) / TB;   // warp-per-row kernels
    const int warpEdgeBlocks = ((size_t)NEDGES * 32 + TB - 1) / TB;

    // --- CSR build (cheap; rebuilt every call for determinism of work) ---
    zero_int_kernel<<<nodeBlocks, TB>>>(deg, NNODES);
    count_deg_kernel<<<edgeBlocks, TB>>>(dst, deg);
    scan_deg_kernel<<<1, 1024>>>(deg, rowptr, cursor);
    fill_col_kernel<<<edgeBlocks, TB>>>(dst, cursor, colb);

    // x working copy
    copy_kernel<<<512, TB>>>(x, xb, NNODES * DIMC);

    auto gemm_grid = [](int M, int N) { return dim3((unsigned)(N / 128), (unsigned)((M + 127) / 128)); };

    for (int d = 0; d < 2; d++) {
        // --- attention block ---
        ln_kernel<<<warpRowBlocks, TB>>>(xb, ln1_g + d * DIMC, ln1_b + d * DIMC, xn, NNODES);

        gemm_kernel<0><<<gemm_grid(NNODES, INNERC), TB>>>(
            xn, Wq + (size_t)d * DIMC * INNERC, bq + d * INNERC, qb, NNODES, DIMC, INNERC);
        gemm_kernel<0><<<gemm_grid(NNODES, 2 * INNERC), TB>>>(
            xn, Wkv + (size_t)d * DIMC * 2 * INNERC, bkv + d * 2 * INNERC, kvb, NNODES, DIMC, 2 * INNERC);
        gemm_kernel<0><<<gemm_grid(NEDGES, INNERC), TB>>>(
            edge_attr, We + (size_t)d * EDIMC * INNERC, be + d * INNERC, eb, NEDGES, EDIMC, INNERC);

        sim_kernel<<<warpEdgeBlocks, TB>>>(qb, kvb, eb, src, dst, simb);
        node_attn_kernel<<<NNODES, TB>>>(kvb, eb, simb, rowptr, colb, src, aggb);

        gemm_kernel<0><<<gemm_grid(NNODES, DIMC), TB>>>(
            aggb, Wo + (size_t)d * INNERC * DIMC, bo + d * DIMC, yb, NNODES, INNERC, DIMC);
        gated_residual_kernel<<<warpRowBlocks, TB>>>(yb, xb, gaw + d * 3 * DIMC, NNODES);

        // --- feedforward block ---
        ln_kernel<<<warpRowBlocks, TB>>>(xb, ln2_g + d * DIMC, ln2_b + d * DIMC, xn, NNODES);
        gemm_kernel<1><<<gemm_grid(NNODES, FFC), TB>>>(
            xn, Wff1 + (size_t)d * DIMC * FFC, bff1 + d * FFC, ffb, NNODES, DIMC, FFC);
        gemm_kernel<0><<<gemm_grid(NNODES, DIMC), TB>>>(
            ffb, Wff2 + (size_t)d * FFC * DIMC, bff2 + d * DIMC, yb, NNODES, FFC, DIMC);
        gated_residual_kernel<<<warpRowBlocks, TB>>>(yb, xb, gfw + d * 3 * DIMC, NNODES);
    }

    // --- output projection ---
    gemm_kernel<0><<<gemm_grid(NNODES, OUTC), TB>>>(
        xb, Wproj, bproj, out, NNODES, DIMC, OUTC);
}